// round 3
// baseline (speedup 1.0000x reference)
#include <cuda_runtime.h>

#define N_FEAT 96
#define MAX_N  50000
#define MAX_E  800000

// Scratch (device globals; no allocation allowed)
__device__ float g_h1[MAX_N * N_FEAT];   // intermediate hop result
__device__ float g_deg[MAX_N];
__device__ float g_dinv[MAX_N];
__device__ float g_norm[MAX_E];
__device__ int   g_src[MAX_E];
__device__ int   g_dst[MAX_E];
__device__ int   g_is64;

// Detect whether edge_index is int64 or int32.
// Only reads within the first 2*E 32-bit words — valid under EITHER dtype
// (that's the full int32 buffer, or the first half of an int64 buffer).
// If int64: odd words are high halves of small nonneg indices -> all zero.
// If int32: odd words are random node indices -> essentially never all zero.
__global__ void k_detect(const unsigned int* __restrict__ ei32, int E) {
    __shared__ unsigned int acc;
    if (threadIdx.x == 0) acc = 0u;
    __syncthreads();
    unsigned int v = 0u;
    int W = 2 * E;                 // safe word count
    int stride = W / 1024;         // >= 1 for any realistic E
    for (int i = threadIdx.x; i < 1024; i += blockDim.x) {
        long long w = (long long)i * stride;
        w |= 1;                    // odd word
        if (w < W) v |= ei32[w];
    }
    atomicOr(&acc, v);
    __syncthreads();
    if (threadIdx.x == 0) g_is64 = (acc == 0u) ? 1 : 0;
}

// Convert indices to int32 arrays (handles either input dtype).
__global__ void k_convert(const void* __restrict__ ei, int E) {
    int e = blockIdx.x * blockDim.x + threadIdx.x;
    if (e >= E) return;
    if (g_is64) {
        const long long* p = (const long long*)ei;
        g_src[e] = (int)p[e];
        g_dst[e] = (int)p[e + E];
    } else {
        const int* p = (const int*)ei;
        g_src[e] = p[e];
        g_dst[e] = p[e + E];
    }
}

// deg[i] = 1 (self loop)
__global__ void k_init_deg(int N) {
    int i = blockIdx.x * blockDim.x + threadIdx.x;
    if (i < N) g_deg[i] = 1.0f;
}

// deg[dst] += 1 per edge
__global__ void k_count_deg(int E) {
    int e = blockIdx.x * blockDim.x + threadIdx.x;
    if (e < E) atomicAdd(&g_deg[g_dst[e]], 1.0f);
}

// dinv = rsqrt(deg)  (deg >= 1 always, no zero guard needed)
__global__ void k_dinv(int N) {
    int i = blockIdx.x * blockDim.x + threadIdx.x;
    if (i < N) g_dinv[i] = rsqrtf(g_deg[i]);
}

// per-edge norm = dinv[src]*dinv[dst]
__global__ void k_norm(int E) {
    int e = blockIdx.x * blockDim.x + threadIdx.x;
    if (e < E) g_norm[e] = g_dinv[g_src[e]] * g_dinv[g_dst[e]];
}

// hout(g_h1) = dinv^2 * hin  (self-loop term; also the initializer of hout)
__global__ void k_self_to_h1(const float4* __restrict__ hin, int N) {
    int idx = blockIdx.x * blockDim.x + threadIdx.x;
    int total = N * (N_FEAT / 4);
    if (idx < total) {
        int node = idx / (N_FEAT / 4);
        float s = g_dinv[node];
        s = s * s;
        float4 v = hin[idx];
        v.x *= s; v.y *= s; v.z *= s; v.w *= s;
        ((float4*)g_h1)[idx] = v;
    }
}

// One warp per edge: g_h1[dst, :] += norm * hin[src, :]
__global__ void k_hop_to_h1(const float* __restrict__ hin, int E) {
    int warp = (blockIdx.x * blockDim.x + threadIdx.x) >> 5;
    int lane = threadIdx.x & 31;
    if (warp >= E) return;
    int s = g_src[warp];
    int d = g_dst[warp];
    float nrm = g_norm[warp];
    const float* pin  = hin + (size_t)s * N_FEAT;
    float*       pout = g_h1 + (size_t)d * N_FEAT;
#pragma unroll
    for (int k = 0; k < 3; k++) {
        int f = lane + k * 32;
        atomicAdd(&pout[f], nrm * pin[f]);
    }
}

// hout = dinv^2 * g_h1
__global__ void k_self_from_h1(float4* __restrict__ hout, int N) {
    int idx = blockIdx.x * blockDim.x + threadIdx.x;
    int total = N * (N_FEAT / 4);
    if (idx < total) {
        int node = idx / (N_FEAT / 4);
        float s = g_dinv[node];
        s = s * s;
        float4 v = ((const float4*)g_h1)[idx];
        v.x *= s; v.y *= s; v.z *= s; v.w *= s;
        hout[idx] = v;
    }
}

// One warp per edge: hout[dst, :] += norm * g_h1[src, :]
__global__ void k_hop_from_h1(float* __restrict__ hout, int E) {
    int warp = (blockIdx.x * blockDim.x + threadIdx.x) >> 5;
    int lane = threadIdx.x & 31;
    if (warp >= E) return;
    int s = g_src[warp];
    int d = g_dst[warp];
    float nrm = g_norm[warp];
    const float* pin  = g_h1 + (size_t)s * N_FEAT;
    float*       pout = hout + (size_t)d * N_FEAT;
#pragma unroll
    for (int k = 0; k < 3; k++) {
        int f = lane + k * 32;
        atomicAdd(&pout[f], nrm * pin[f]);
    }
}

extern "C" void kernel_launch(void* const* d_in, const int* in_sizes, int n_in,
                              void* d_out, int out_size) {
    const float* x  = (const float*)d_in[0];
    const void*  ei = d_in[1];
    int N = in_sizes[0] / N_FEAT;      // 50000
    int E = in_sizes[1] / 2;           // 800000
    float* out = (float*)d_out;

    const int T = 256;

    // dtype detection + index conversion
    k_detect<<<1, 256>>>((const unsigned int*)ei, E);
    k_convert<<<(E + T - 1) / T, T>>>(ei, E);

    // degree + norm precompute
    k_init_deg<<<(N + T - 1) / T, T>>>(N);
    k_count_deg<<<(E + T - 1) / T, T>>>(E);
    k_dinv<<<(N + T - 1) / T, T>>>(N);
    k_norm<<<(E + T - 1) / T, T>>>(E);

    int selfBlocks = (N * (N_FEAT / 4) + T - 1) / T;
    int hopBlocks  = (E + (T / 32) - 1) / (T / 32);   // one warp per edge

    // hop 1: x -> g_h1
    k_self_to_h1<<<selfBlocks, T>>>((const float4*)x, N);
    k_hop_to_h1<<<hopBlocks, T>>>(x, E);

    // hop 2: g_h1 -> out
    k_self_from_h1<<<selfBlocks, T>>>((float4*)out, N);
    k_hop_from_h1<<<hopBlocks, T>>>(out, E);
}